// round 1
// baseline (speedup 1.0000x reference)
#include <cuda_runtime.h>

#define DEV_INLINE __device__ __forceinline__

namespace {
constexpr int Bsz    = 32768;
constexpr int Adim   = 8;
constexpr int Fdim   = 256;
constexpr int Hdim   = 256;
constexpr int NSTEPS = 50;
constexpr int TB     = 64;    // batch rows per CTA
constexpr int NT     = 256;   // threads per CTA (8 warps, each owns 8 rows)
constexpr float DTC  = 1.0f / 50.0f;

// smem layout (floats)
constexpr int SMEM_FLOATS =
    3 * TB * Hdim       // c_base, h1, g1
    + 16 * 128          // W2/W1b stage chunk
    + 8 * Hdim          // W1 rows 0..7 (action part)
    + Hdim              // W1 row 264 (t part)
    + Hdim * Adim       // W3
    + Hdim              // b2
    + Adim              // b3
    + 4 * TB * Adim     // a, e, v, jv
    + TB;               // div_int
constexpr int SMEM_BYTES = SMEM_FLOATS * 4;   // 231,712 B <= 232,448 (227 KB)

DEV_INLINE void fma4(float4& acc, float h, const float4& w) {
    acc.x += h * w.x; acc.y += h * w.y; acc.z += h * w.z; acc.w += h * w.w;
}
}  // namespace

__global__ void __launch_bounds__(NT, 1) fm_logp_kernel(
    const float* __restrict__ actions,   // [B, 8]
    const float* __restrict__ feats,     // [B, 256]
    const float* __restrict__ W1,        // [265, 256]
    const float* __restrict__ b1,        // [256]
    const float* __restrict__ W2,        // [256, 256]
    const float* __restrict__ b2g,       // [256]
    const float* __restrict__ W3,        // [256, 8]
    const float* __restrict__ b3g,       // [8]
    const float* __restrict__ eps,       // [50, B, 8]
    float* __restrict__ out)             // [B]
{
    extern __shared__ float sm[];
    float* c_base = sm;                       // [TB][256]
    float* h1     = c_base + TB * Hdim;       // [TB][256]
    float* g1     = h1 + TB * Hdim;           // [TB][256]
    float* wst    = g1 + TB * Hdim;           // [16][128]
    float* w1a    = wst + 16 * 128;           // [8][256]
    float* w1t    = w1a + 8 * Hdim;           // [256]
    float* w3s    = w1t + Hdim;               // [256][8]
    float* b2s    = w3s + Hdim * Adim;        // [256]
    float* b3s    = b2s + Hdim;               // [8]
    float* a_s    = b3s + Adim;               // [TB][8]
    float* e_s    = a_s + TB * Adim;          // [TB][8]
    float* v_s    = e_s + TB * Adim;          // [TB][8]
    float* jv_s   = v_s + TB * Adim;          // [TB][8]
    float* di_s   = jv_s + TB * Adim;         // [TB]

    const int tid  = threadIdx.x;
    const int lane = tid & 31;
    const int warp = tid >> 5;
    const int row0 = blockIdx.x * TB;
    const int wr0  = warp * 8;                // warp's first local row

    // ---------------- setup: weights/state into smem ----------------
    for (int i = tid; i < 8 * Hdim; i += NT)     w1a[i] = W1[i];
    for (int i = tid; i < Hdim; i += NT)         w1t[i] = W1[(Adim + Fdim) * Hdim + i];
    for (int i = tid; i < Hdim * Adim; i += NT)  w3s[i] = W3[i];
    for (int i = tid; i < Hdim; i += NT)         b2s[i] = b2g[i];
    if (tid < Adim) b3s[tid] = b3g[tid];
    for (int i = tid; i < TB * Adim; i += NT)    a_s[i] = actions[row0 * Adim + i];
    if (tid < TB) di_s[tid] = 0.0f;

    // stage C tile (actor features) into h1 temporarily
    for (int r = 0; r < TB; r++)
        h1[r * Hdim + tid] = feats[(row0 + r) * Fdim + tid];
    __syncthreads();

    // ---------------- c_base = C @ W1[8:264] + b1 ----------------
    for (int p = 0; p < 2; p++) {
        const int jbase = p * 128 + lane * 4;
        float4 acc[8];
        #pragma unroll
        for (int r = 0; r < 8; r++) acc[r] = make_float4(0.f, 0.f, 0.f, 0.f);

        for (int kb = 0; kb < Fdim; kb += 16) {
            __syncthreads();
            {
                int f = tid;
                int kk = f >> 5, jj = (f & 31) << 2;
                *(float4*)&wst[kk * 128 + jj] =
                    *(const float4*)&W1[(Adim + kb + kk) * Hdim + p * 128 + jj];
                f = tid + NT; kk = f >> 5; jj = (f & 31) << 2;
                *(float4*)&wst[kk * 128 + jj] =
                    *(const float4*)&W1[(Adim + kb + kk) * Hdim + p * 128 + jj];
            }
            __syncthreads();
            #pragma unroll
            for (int kk = 0; kk < 16; kk += 4) {
                float4 wv0 = *(float4*)&wst[(kk + 0) * 128 + lane * 4];
                float4 wv1 = *(float4*)&wst[(kk + 1) * 128 + lane * 4];
                float4 wv2 = *(float4*)&wst[(kk + 2) * 128 + lane * 4];
                float4 wv3 = *(float4*)&wst[(kk + 3) * 128 + lane * 4];
                #pragma unroll
                for (int r = 0; r < 8; r++) {
                    float4 c4 = *(float4*)&h1[(wr0 + r) * Hdim + kb + kk];
                    fma4(acc[r], c4.x, wv0);
                    fma4(acc[r], c4.y, wv1);
                    fma4(acc[r], c4.z, wv2);
                    fma4(acc[r], c4.w, wv3);
                }
            }
        }
        float4 bb = *(const float4*)&b1[jbase];
        #pragma unroll
        for (int r = 0; r < 8; r++) {
            float4 o = make_float4(acc[r].x + bb.x, acc[r].y + bb.y,
                                   acc[r].z + bb.z, acc[r].w + bb.w);
            *(float4*)&c_base[(wr0 + r) * Hdim + jbase] = o;
        }
    }
    __syncthreads();

    // ---------------- 50 reverse-Euler steps ----------------
    for (int step = 0; step < NSTEPS; step++) {
        const float t = 1.0f - (float)step * DTC;

        __syncthreads();  // prev-step a_s/di_s writes, e_s reads done
        for (int i = tid; i < TB * Adim; i += NT)
            e_s[i] = eps[(long)step * Bsz * Adim + row0 * Adim + i];
        // per-warp init of v/jv accumulators for this warp's 8 rows
        if (lane < 16) {
            #pragma unroll
            for (int r = 0; r < 8; r++) {
                if (lane < 8) v_s[(wr0 + r) * Adim + lane] = b3s[lane];
                else          jv_s[(wr0 + r) * Adim + lane - 8] = 0.0f;
            }
        }
        __syncthreads();  // e_s visible

        // ---- phase A: z1/dz1 -> h1, g1 ----
        #pragma unroll 2
        for (int r = 0; r < TB; r++) {
            float z  = c_base[r * Hdim + tid] + t * w1t[tid];
            float dz = 0.0f;
            #pragma unroll
            for (int k = 0; k < Adim; k++) {
                float w = w1a[k * Hdim + tid];
                z  += a_s[r * Adim + k] * w;
                dz += e_s[r * Adim + k] * w;
            }
            float s = 1.0f / (1.0f + __expf(-z));
            h1[r * Hdim + tid] = z * s;
            g1[r * Hdim + tid] = dz * (s * (1.0f + z * (1.0f - s)));
        }

        // ---- phase B: z2/dz2 GEMM + fused silu + GEMM3 epilogue ----
        for (int p = 0; p < 2; p++) {
            const int jbase = p * 128 + lane * 4;
            float4 za[8], ga[8];
            #pragma unroll
            for (int r = 0; r < 8; r++) {
                za[r] = make_float4(0.f, 0.f, 0.f, 0.f);
                ga[r] = make_float4(0.f, 0.f, 0.f, 0.f);
            }

            for (int kb = 0; kb < Hdim; kb += 16) {
                __syncthreads();
                {
                    int f = tid;
                    int kk = f >> 5, jj = (f & 31) << 2;
                    *(float4*)&wst[kk * 128 + jj] =
                        *(const float4*)&W2[(kb + kk) * Hdim + p * 128 + jj];
                    f = tid + NT; kk = f >> 5; jj = (f & 31) << 2;
                    *(float4*)&wst[kk * 128 + jj] =
                        *(const float4*)&W2[(kb + kk) * Hdim + p * 128 + jj];
                }
                __syncthreads();
                #pragma unroll
                for (int kk = 0; kk < 16; kk += 4) {
                    float4 wv0 = *(float4*)&wst[(kk + 0) * 128 + lane * 4];
                    float4 wv1 = *(float4*)&wst[(kk + 1) * 128 + lane * 4];
                    float4 wv2 = *(float4*)&wst[(kk + 2) * 128 + lane * 4];
                    float4 wv3 = *(float4*)&wst[(kk + 3) * 128 + lane * 4];
                    #pragma unroll
                    for (int r = 0; r < 8; r++) {
                        float4 h4 = *(float4*)&h1[(wr0 + r) * Hdim + kb + kk];
                        float4 g4 = *(float4*)&g1[(wr0 + r) * Hdim + kb + kk];
                        fma4(za[r], h4.x, wv0); fma4(ga[r], g4.x, wv0);
                        fma4(za[r], h4.y, wv1); fma4(ga[r], g4.y, wv1);
                        fma4(za[r], h4.z, wv2); fma4(ga[r], g4.z, wv2);
                        fma4(za[r], h4.w, wv3); fma4(ga[r], g4.w, wv3);
                    }
                }
            }

            // epilogue: silu(z2), tangent, project through W3, reduce over lanes
            float4 bb = *(float4*)&b2s[jbase];
            #pragma unroll
            for (int r = 0; r < 8; r++) {
                float zc[4] = {za[r].x + bb.x, za[r].y + bb.y,
                               za[r].z + bb.z, za[r].w + bb.w};
                float dc[4] = {ga[r].x, ga[r].y, ga[r].z, ga[r].w};
                float vp[8], jp[8];
                #pragma unroll
                for (int i = 0; i < 8; i++) { vp[i] = 0.f; jp[i] = 0.f; }
                #pragma unroll
                for (int c = 0; c < 4; c++) {
                    float z = zc[c];
                    float s = 1.0f / (1.0f + __expf(-z));
                    float h2 = z * s;
                    float g2 = dc[c] * (s * (1.0f + z * (1.0f - s)));
                    const float* w3r = &w3s[(jbase + c) * Adim];
                    #pragma unroll
                    for (int i = 0; i < 8; i++) {
                        vp[i] += h2 * w3r[i];
                        jp[i] += g2 * w3r[i];
                    }
                }
                #pragma unroll
                for (int off = 16; off >= 1; off >>= 1) {
                    #pragma unroll
                    for (int i = 0; i < 8; i++) {
                        vp[i] += __shfl_xor_sync(0xffffffffu, vp[i], off);
                        jp[i] += __shfl_xor_sync(0xffffffffu, jp[i], off);
                    }
                }
                if (lane == 0) {
                    #pragma unroll
                    for (int i = 0; i < 8; i++)
                        v_s[(wr0 + r) * Adim + i] += vp[i];
                } else if (lane == 1) {
                    #pragma unroll
                    for (int i = 0; i < 8; i++)
                        jv_s[(wr0 + r) * Adim + i] += jp[i];
                }
            }
        }

        // ---- phase C: euler update + divergence integral (warp-local rows) ----
        __syncwarp();
        if (lane < 8) {
            const int row = wr0 + lane;
            float div = 0.0f;
            #pragma unroll
            for (int i = 0; i < Adim; i++)
                div += jv_s[row * Adim + i] * e_s[row * Adim + i];
            di_s[row] += div * DTC;
            #pragma unroll
            for (int i = 0; i < Adim; i++)
                a_s[row * Adim + i] -= v_s[row * Adim + i] * DTC;
        }
    }

    // ---------------- output: logp = log N(a0) - div_int ----------------
    __syncthreads();
    if (tid < TB) {
        float s2 = 0.0f;
        #pragma unroll
        for (int i = 0; i < Adim; i++) {
            float av = a_s[tid * Adim + i];
            s2 += av * av;
        }
        // ln(2*pi) = 1.8378770664093453
        out[row0 + tid] = -0.5f * (s2 + (float)Adim * 1.8378770664093453f) - di_s[tid];
    }
}

extern "C" void kernel_launch(void* const* d_in, const int* in_sizes, int n_in,
                              void* d_out, int out_size) {
    (void)in_sizes; (void)n_in; (void)out_size;
    cudaFuncSetAttribute(fm_logp_kernel,
                         cudaFuncAttributeMaxDynamicSharedMemorySize, SMEM_BYTES);
    fm_logp_kernel<<<Bsz / TB, NT, SMEM_BYTES>>>(
        (const float*)d_in[0],   // actions
        (const float*)d_in[1],   // actor_features
        (const float*)d_in[2],   // W1
        (const float*)d_in[3],   // b1
        (const float*)d_in[4],   // W2
        (const float*)d_in[5],   // b2
        (const float*)d_in[6],   // W3
        (const float*)d_in[7],   // b3
        (const float*)d_in[8],   // eps
        (float*)d_out);
}

// round 2
// speedup vs baseline: 1.2032x; 1.2032x over previous
#include <cuda_runtime.h>

typedef unsigned long long ull;

namespace {
constexpr int Bsz    = 32768;
constexpr int Adim   = 8;
constexpr int Hdim   = 256;
constexpr int NSTEPS = 50;
constexpr int TB     = 64;    // batch rows per CTA
constexpr int NT     = 512;   // 16 warps; warp owns 4 rows; lane owns 8 cols
constexpr int KC     = 16;    // k-chunk staged in smem
constexpr int HS     = 260;   // padded row stride (floats) for c_base/h1/g1
constexpr int W3S    = 264;   // padded row stride for transposed W3
constexpr float DTC  = 1.0f / 50.0f;

constexpr int SMEM_FLOATS =
    3 * TB * HS        // c_base, h1, g1 (padded)
    + KC * Hdim        // weight stage chunk
    + 8 * W3S          // W3 transposed [8][264]
    + Hdim             // b2
    + 2 * TB * Adim    // a_s, e_s
    + TB;              // di_s
constexpr int SMEM_BYTES = SMEM_FLOATS * 4;   // 229,888 B
}  // namespace

__device__ __forceinline__ ull pack2(float x) {
    ull r; asm("mov.b64 %0, {%1, %1};" : "=l"(r) : "f"(x)); return r;
}
__device__ __forceinline__ void fma2(ull& d, ull a, ull b) {
    asm("fma.rn.f32x2 %0, %1, %2, %0;" : "+l"(d) : "l"(a), "l"(b));
}
__device__ __forceinline__ void unpack2(ull v, float& lo, float& hi) {
    asm("mov.b64 {%0, %1}, %2;" : "=f"(lo), "=f"(hi) : "l"(v));
}
__device__ __forceinline__ float silu_pair(float z, float& dcoef) {
    float s = 1.0f / (1.0f + __expf(-z));
    dcoef = s * (1.0f + z * (1.0f - s));   // d/dz [z*sigmoid(z)]
    return z * s;
}

__global__ void __launch_bounds__(NT, 1) fm_logp_kernel(
    const float* __restrict__ actions,   // [B, 8]
    const float* __restrict__ feats,     // [B, 256]
    const float* __restrict__ W1,        // [265, 256]
    const float* __restrict__ b1,        // [256]
    const float* __restrict__ W2,        // [256, 256]
    const float* __restrict__ b2g,       // [256]
    const float* __restrict__ W3,        // [256, 8]
    const float* __restrict__ b3g,       // [8]
    const float* __restrict__ eps,       // [50, B, 8]
    float* __restrict__ out)             // [B]
{
    extern __shared__ float sm[];
    float* c_base = sm;                    // [TB][HS]
    float* h1     = c_base + TB * HS;      // [TB][HS]
    float* g1     = h1 + TB * HS;          // [TB][HS]
    float* wst    = g1 + TB * HS;          // [KC][256]
    float* w3t    = wst + KC * Hdim;       // [8][W3S]  (transposed W3)
    float* b2s    = w3t + 8 * W3S;         // [256]
    float* a_s    = b2s + Hdim;            // [TB][8]
    float* e_s    = a_s + TB * Adim;       // [TB][8]
    float* di_s   = e_s + TB * Adim;       // [TB]

    const int tid  = threadIdx.x;
    const int lane = tid & 31;
    const int warp = tid >> 5;             // 0..15
    const int wr0  = warp * 4;             // warp's first local row
    const int row0 = blockIdx.x * TB;
    const int jb   = lane * 8;             // lane's first output column

    // phase-A mapping: thread handles column `colA` for rows rh, rh+2, ...
    const int colA = tid & 255;
    const int rh   = tid >> 8;             // 0 or 1
    // GEMM3 mapping: thread handles (row g3r, out-dim g3i)
    const int g3r  = tid >> 3;             // 0..63
    const int g3i  = tid & 7;              // 0..7

    // ---------------- setup ----------------
    // W3 transposed into smem
    for (int idx = tid; idx < Hdim * Adim; idx += NT)
        w3t[(idx & 7) * W3S + (idx >> 3)] = W3[idx];
    if (tid < Hdim) b2s[tid] = b2g[tid];
    a_s[tid < TB * Adim ? tid : 0] = 0.0f;  // dummy to keep uniform; real load below
    a_s[tid & (TB * Adim - 1)] = actions[row0 * Adim + (tid & (TB * Adim - 1))];
    if (tid < TB) di_s[tid] = 0.0f;

    // per-thread register copies
    float w1a_r[Adim];
    #pragma unroll
    for (int k = 0; k < Adim; k++) w1a_r[k] = W1[k * Hdim + colA];
    const float w1t_r = W1[(Adim + Hdim) * Hdim + colA];   // t row (index 264)
    const float b3_r  = b3g[g3i];

    // stage actor features into h1 (temporarily)
    for (int idx = tid; idx < TB * Hdim; idx += NT)
        h1[(idx >> 8) * HS + (idx & 255)] = feats[row0 * Hdim + idx];
    __syncthreads();

    // ---------------- c_base = feats @ W1[8:264] + b1 ----------------
    {
        ull acc[4][4];
        #pragma unroll
        for (int r = 0; r < 4; r++)
            #pragma unroll
            for (int c = 0; c < 4; c++) acc[r][c] = 0ull;

        for (int kb = 0; kb < Hdim; kb += KC) {
            __syncthreads();
            {
                int i = tid;            int rr = i >> 6, cf = (i & 63) << 2;
                *(float4*)&wst[rr * Hdim + cf] =
                    *(const float4*)&W1[(Adim + kb + rr) * Hdim + cf];
                i = tid + NT;           rr = i >> 6;  cf = (i & 63) << 2;
                *(float4*)&wst[rr * Hdim + cf] =
                    *(const float4*)&W1[(Adim + kb + rr) * Hdim + cf];
            }
            __syncthreads();
            #pragma unroll
            for (int kk = 0; kk < KC; kk += 4) {
                float hb[4][4];
                #pragma unroll
                for (int r = 0; r < 4; r++)
                    *(float4*)hb[r] = *(const float4*)&h1[(wr0 + r) * HS + kb + kk];
                #pragma unroll
                for (int j = 0; j < 4; j++) {
                    const float* wr_ = &wst[(kk + j) * Hdim + jb];
                    ulonglong2 w01 = *(const ulonglong2*)wr_;
                    ulonglong2 w23 = *(const ulonglong2*)(wr_ + 4);
                    #pragma unroll
                    for (int r = 0; r < 4; r++) {
                        ull hp = pack2(hb[r][j]);
                        fma2(acc[r][0], hp, w01.x);
                        fma2(acc[r][1], hp, w01.y);
                        fma2(acc[r][2], hp, w23.x);
                        fma2(acc[r][3], hp, w23.y);
                    }
                }
            }
        }
        float4 bb0 = *(const float4*)&b1[jb];
        float4 bb1 = *(const float4*)&b1[jb + 4];
        #pragma unroll
        for (int r = 0; r < 4; r++) {
            float o[8];
            unpack2(acc[r][0], o[0], o[1]);
            unpack2(acc[r][1], o[2], o[3]);
            unpack2(acc[r][2], o[4], o[5]);
            unpack2(acc[r][3], o[6], o[7]);
            o[0] += bb0.x; o[1] += bb0.y; o[2] += bb0.z; o[3] += bb0.w;
            o[4] += bb1.x; o[5] += bb1.y; o[6] += bb1.z; o[7] += bb1.w;
            *(float4*)&c_base[(wr0 + r) * HS + jb]     = make_float4(o[0], o[1], o[2], o[3]);
            *(float4*)&c_base[(wr0 + r) * HS + jb + 4] = make_float4(o[4], o[5], o[6], o[7]);
        }
    }

    // ---------------- 50 reverse-Euler steps ----------------
    for (int step = 0; step < NSTEPS; step++) {
        const float t = 1.0f - (float)step * DTC;

        __syncthreads();   // prior GEMM3 a_s writes + e_s readers done
        e_s[tid & (TB * Adim - 1)] =
            eps[(size_t)step * Bsz * Adim + row0 * Adim + (tid & (TB * Adim - 1))];
        __syncthreads();

        // ---- phase A: layer-1 value + tangent, silu ----
        #pragma unroll 4
        for (int r = rh; r < TB; r += 2) {
            float4 a0 = *(const float4*)&a_s[r * Adim];
            float4 a1 = *(const float4*)&a_s[r * Adim + 4];
            float4 e0 = *(const float4*)&e_s[r * Adim];
            float4 e1 = *(const float4*)&e_s[r * Adim + 4];
            float z = c_base[r * HS + colA] + t * w1t_r;
            z += a0.x * w1a_r[0] + a0.y * w1a_r[1] + a0.z * w1a_r[2] + a0.w * w1a_r[3]
               + a1.x * w1a_r[4] + a1.y * w1a_r[5] + a1.z * w1a_r[6] + a1.w * w1a_r[7];
            float dz = e0.x * w1a_r[0] + e0.y * w1a_r[1] + e0.z * w1a_r[2] + e0.w * w1a_r[3]
                     + e1.x * w1a_r[4] + e1.y * w1a_r[5] + e1.z * w1a_r[6] + e1.w * w1a_r[7];
            float dc;
            float h = silu_pair(z, dc);
            h1[r * HS + colA] = h;
            g1[r * HS + colA] = dz * dc;
        }
        __syncthreads();

        // ---- phase B: z2/dz2 GEMM (packed f32x2) ----
        ull za[4][4], ga[4][4];
        #pragma unroll
        for (int r = 0; r < 4; r++)
            #pragma unroll
            for (int c = 0; c < 4; c++) { za[r][c] = 0ull; ga[r][c] = 0ull; }

        for (int kb = 0; kb < Hdim; kb += KC) {
            __syncthreads();
            {
                int i = tid;            int rr = i >> 6, cf = (i & 63) << 2;
                *(float4*)&wst[rr * Hdim + cf] =
                    *(const float4*)&W2[(kb + rr) * Hdim + cf];
                i = tid + NT;           rr = i >> 6;  cf = (i & 63) << 2;
                *(float4*)&wst[rr * Hdim + cf] =
                    *(const float4*)&W2[(kb + rr) * Hdim + cf];
            }
            __syncthreads();
            #pragma unroll
            for (int kk = 0; kk < KC; kk += 4) {
                float hb[4][4], gb[4][4];
                #pragma unroll
                for (int r = 0; r < 4; r++) {
                    *(float4*)hb[r] = *(const float4*)&h1[(wr0 + r) * HS + kb + kk];
                    *(float4*)gb[r] = *(const float4*)&g1[(wr0 + r) * HS + kb + kk];
                }
                #pragma unroll
                for (int j = 0; j < 4; j++) {
                    const float* wr_ = &wst[(kk + j) * Hdim + jb];
                    ulonglong2 w01 = *(const ulonglong2*)wr_;
                    ulonglong2 w23 = *(const ulonglong2*)(wr_ + 4);
                    #pragma unroll
                    for (int r = 0; r < 4; r++) {
                        ull hp = pack2(hb[r][j]);
                        ull gp = pack2(gb[r][j]);
                        fma2(za[r][0], hp, w01.x);
                        fma2(za[r][1], hp, w01.y);
                        fma2(za[r][2], hp, w23.x);
                        fma2(za[r][3], hp, w23.y);
                        fma2(ga[r][0], gp, w01.x);
                        fma2(ga[r][1], gp, w01.y);
                        fma2(ga[r][2], gp, w23.x);
                        fma2(ga[r][3], gp, w23.y);
                    }
                }
            }
        }

        // ---- epilogue: silu(z2) + tangent -> overwrite h1/g1 (own rows only) ----
        {
            float4 bb0 = *(const float4*)&b2s[jb];
            float4 bb1 = *(const float4*)&b2s[jb + 4];
            float bv[8] = {bb0.x, bb0.y, bb0.z, bb0.w, bb1.x, bb1.y, bb1.z, bb1.w};
            #pragma unroll
            for (int r = 0; r < 4; r++) {
                float zz[8], gg[8];
                unpack2(za[r][0], zz[0], zz[1]);
                unpack2(za[r][1], zz[2], zz[3]);
                unpack2(za[r][2], zz[4], zz[5]);
                unpack2(za[r][3], zz[6], zz[7]);
                unpack2(ga[r][0], gg[0], gg[1]);
                unpack2(ga[r][1], gg[2], gg[3]);
                unpack2(ga[r][2], gg[4], gg[5]);
                unpack2(ga[r][3], gg[6], gg[7]);
                float hh[8];
                #pragma unroll
                for (int c = 0; c < 8; c++) {
                    float dc;
                    hh[c] = silu_pair(zz[c] + bv[c], dc);
                    gg[c] = gg[c] * dc;
                }
                *(float4*)&h1[(wr0 + r) * HS + jb]     = make_float4(hh[0], hh[1], hh[2], hh[3]);
                *(float4*)&h1[(wr0 + r) * HS + jb + 4] = make_float4(hh[4], hh[5], hh[6], hh[7]);
                *(float4*)&g1[(wr0 + r) * HS + jb]     = make_float4(gg[0], gg[1], gg[2], gg[3]);
                *(float4*)&g1[(wr0 + r) * HS + jb + 4] = make_float4(gg[4], gg[5], gg[6], gg[7]);
            }
        }
        __syncthreads();

        // ---- GEMM3 + Euler update: thread (g3r, g3i) ----
        {
            const float* hp_ = &h1[g3r * HS];
            const float* gp_ = &g1[g3r * HS];
            const float* wp_ = &w3t[g3i * W3S];
            float v = 0.0f, jv = 0.0f;
            #pragma unroll 8
            for (int cb = 0; cb < Hdim; cb += 4) {
                float4 h4 = *(const float4*)&hp_[cb];
                float4 g4 = *(const float4*)&gp_[cb];
                float4 w4 = *(const float4*)&wp_[cb];
                v  += h4.x * w4.x + h4.y * w4.y + h4.z * w4.z + h4.w * w4.w;
                jv += g4.x * w4.x + g4.y * w4.y + g4.z * w4.z + g4.w * w4.w;
            }
            float dp = jv * e_s[g3r * Adim + g3i];
            dp += __shfl_xor_sync(0xffffffffu, dp, 1);
            dp += __shfl_xor_sync(0xffffffffu, dp, 2);
            dp += __shfl_xor_sync(0xffffffffu, dp, 4);
            a_s[g3r * Adim + g3i] -= (v + b3_r) * DTC;
            if (g3i == 0) di_s[g3r] += dp * DTC;
        }
    }

    // ---------------- output ----------------
    __syncthreads();
    if (tid < TB) {
        float s2 = 0.0f;
        #pragma unroll
        for (int i = 0; i < Adim; i++) {
            float av = a_s[tid * Adim + i];
            s2 += av * av;
        }
        out[row0 + tid] = -0.5f * (s2 + (float)Adim * 1.8378770664093453f) - di_s[tid];
    }
}

extern "C" void kernel_launch(void* const* d_in, const int* in_sizes, int n_in,
                              void* d_out, int out_size) {
    (void)in_sizes; (void)n_in; (void)out_size;
    cudaFuncSetAttribute(fm_logp_kernel,
                         cudaFuncAttributeMaxDynamicSharedMemorySize, SMEM_BYTES);
    fm_logp_kernel<<<Bsz / TB, NT, SMEM_BYTES>>>(
        (const float*)d_in[0],   // actions
        (const float*)d_in[1],   // actor_features
        (const float*)d_in[2],   // W1
        (const float*)d_in[3],   // b1
        (const float*)d_in[4],   // W2
        (const float*)d_in[5],   // b2
        (const float*)d_in[6],   // W3
        (const float*)d_in[7],   // b3
        (const float*)d_in[8],   // eps
        (float*)d_out);
}

// round 4
// speedup vs baseline: 3.5916x; 2.9852x over previous
#include <cuda_runtime.h>
#include <cuda_fp16.h>
#include <cstdint>

typedef unsigned long long ull;

namespace {
constexpr int Bsz = 32768, Adim = 8, Hdim = 256, NSTEPS = 50;
constexpr int TB = 64, NT = 512;
constexpr float DTC = 1.0f / 50.0f;

// byte offsets within 1024-aligned smem base
constexpr int OFF_X   = 0;        // 65536: X f16 [128 rows][256 k] blocked swizzle (setup: c_base f32 [64][256])
constexpr int OFF_W2T = 65536;    // 131072: W2^T f16 [256 n][256 k] blocked swizzle (setup: feats f32 [64][260])
constexpr int OFF_VP  = 196608;   // 8192: v partials [4][64][8] f32 (setup: wst [16][256] spans VP+JP)
constexpr int OFF_JP  = 204800;   // 8192: jv partials
constexpr int OFF_W3  = 212992;   // 8192: W3 [256][8] f32
constexpr int OFF_B2  = 221184;   // 1024
constexpr int OFF_AS  = 222208;   // 2048: a_s [64][8]
constexpr int OFF_ES  = 224256;   // 2048: e_s [64][8]
constexpr int OFF_DI  = 226304;   // 256
constexpr int SMEM_BYTES = 226560 + 1024;
}  // namespace

__device__ __forceinline__ uint32_t cvta_smem(const void* p) {
    uint32_t a;
    asm("{ .reg .u64 t; cvta.to.shared.u64 t, %1; cvt.u32.u64 %0, t; }" : "=r"(a) : "l"(p));
    return a;
}
__device__ __forceinline__ uint32_t swz(uint32_t o) { return o ^ ((o >> 3) & 0x70u); }
// blocked K-major layouts: atom = 8 rows x 128B (64 f16); atoms advance row-major then k-block
__device__ __forceinline__ uint32_t xbyte(int row, int k) {   // X: 128 rows
    return (uint32_t)((((row >> 3) + ((k >> 6) << 4)) << 10) + ((row & 7) << 7) + ((k & 63) << 1));
}
__device__ __forceinline__ ull pack2(float x) { ull r; asm("mov.b64 %0,{%1,%1};" : "=l"(r) : "f"(x)); return r; }
__device__ __forceinline__ void fma2(ull& d, ull a, ull b) { asm("fma.rn.f32x2 %0,%1,%2,%0;" : "+l"(d) : "l"(a), "l"(b)); }
__device__ __forceinline__ void unpack2(ull v, float& lo, float& hi) { asm("mov.b64 {%0,%1},%2;" : "=f"(lo), "=f"(hi) : "l"(v)); }

__device__ __forceinline__ void ldsm4(uint32_t& r0, uint32_t& r1, uint32_t& r2, uint32_t& r3, uint32_t a) {
    asm volatile("ldmatrix.sync.aligned.m8n8.x4.shared.b16 {%0,%1,%2,%3}, [%4];"
                 : "=r"(r0), "=r"(r1), "=r"(r2), "=r"(r3) : "r"(a));
}
__device__ __forceinline__ void mma16816(float* c, uint32_t a0, uint32_t a1, uint32_t a2, uint32_t a3,
                                         uint32_t b0, uint32_t b1) {
    asm volatile("mma.sync.aligned.m16n8k16.row.col.f32.f16.f16.f32 "
                 "{%0,%1,%2,%3}, {%4,%5,%6,%7}, {%8,%9}, {%0,%1,%2,%3};"
                 : "+f"(c[0]), "+f"(c[1]), "+f"(c[2]), "+f"(c[3])
                 : "r"(a0), "r"(a1), "r"(a2), "r"(a3), "r"(b0), "r"(b1));
}

__global__ void __launch_bounds__(NT, 1) fm_logp_kernel(
    const float* __restrict__ actions, const float* __restrict__ feats,
    const float* __restrict__ W1, const float* __restrict__ b1,
    const float* __restrict__ W2, const float* __restrict__ b2g,
    const float* __restrict__ W3g, const float* __restrict__ b3g,
    const float* __restrict__ eps, float* __restrict__ out)
{
    extern __shared__ char smraw[];
    const uint32_t base0 = cvta_smem(smraw);
    const uint32_t smb = (base0 + 1023u) & ~1023u;
    char* smc = smraw + (smb - base0);

    float* vp_s = (float*)(smc + OFF_VP);
    float* jp_s = (float*)(smc + OFF_JP);
    float* w3s  = (float*)(smc + OFF_W3);
    float* b2s  = (float*)(smc + OFF_B2);
    float* a_s  = (float*)(smc + OFF_AS);
    float* e_s  = (float*)(smc + OFF_ES);
    float* di_s = (float*)(smc + OFF_DI);

    const int tid  = threadIdx.x;
    const int lane = tid & 31;
    const int warp = tid >> 5;
    const int row0 = blockIdx.x * TB;

    // ================= setup: c_base = feats @ W1[8:264] + b1 (fp32, one-time) =================
    {
        float* featss = (float*)(smc + OFF_W2T);  // [64][260]
        float* wstp   = (float*)(smc + OFF_VP);   // [16][256] (spans VP+JP)
        float* cb32   = (float*)(smc + OFF_X);    // [64][256]

        for (int idx = tid; idx < TB * Hdim; idx += NT)
            featss[(idx >> 8) * 260 + (idx & 255)] = feats[row0 * Hdim + idx];
        if (tid < TB * Adim) a_s[tid] = actions[row0 * Adim + tid];
        if (tid < TB) di_s[tid] = 0.0f;
        __syncthreads();

        const int wr0 = warp * 4, jb = lane * 8;
        ull acc[4][4];
        #pragma unroll
        for (int r = 0; r < 4; r++)
            #pragma unroll
            for (int c = 0; c < 4; c++) acc[r][c] = 0ull;

        for (int kb = 0; kb < Hdim; kb += 16) {
            __syncthreads();
            {
                int i = tid;      int rr = i >> 6, cf = (i & 63) << 2;
                *(float4*)&wstp[rr * 256 + cf] = *(const float4*)&W1[(Adim + kb + rr) * Hdim + cf];
                i = tid + NT;     rr = i >> 6;  cf = (i & 63) << 2;
                *(float4*)&wstp[rr * 256 + cf] = *(const float4*)&W1[(Adim + kb + rr) * Hdim + cf];
            }
            __syncthreads();
            #pragma unroll
            for (int kk = 0; kk < 16; kk += 4) {
                float hb[4][4];
                #pragma unroll
                for (int r = 0; r < 4; r++)
                    *(float4*)hb[r] = *(const float4*)&featss[(wr0 + r) * 260 + kb + kk];
                #pragma unroll
                for (int j = 0; j < 4; j++) {
                    const float* wr_ = &wstp[(kk + j) * 256 + jb];
                    ulonglong2 w01 = *(const ulonglong2*)wr_;
                    ulonglong2 w23 = *(const ulonglong2*)(wr_ + 4);
                    #pragma unroll
                    for (int r = 0; r < 4; r++) {
                        ull hp = pack2(hb[r][j]);
                        fma2(acc[r][0], hp, w01.x); fma2(acc[r][1], hp, w01.y);
                        fma2(acc[r][2], hp, w23.x); fma2(acc[r][3], hp, w23.y);
                    }
                }
            }
        }
        __syncthreads();
        float4 bb0 = *(const float4*)&b1[jb];
        float4 bb1 = *(const float4*)&b1[jb + 4];
        #pragma unroll
        for (int r = 0; r < 4; r++) {
            float o[8];
            unpack2(acc[r][0], o[0], o[1]); unpack2(acc[r][1], o[2], o[3]);
            unpack2(acc[r][2], o[4], o[5]); unpack2(acc[r][3], o[6], o[7]);
            o[0] += bb0.x; o[1] += bb0.y; o[2] += bb0.z; o[3] += bb0.w;
            o[4] += bb1.x; o[5] += bb1.y; o[6] += bb1.z; o[7] += bb1.w;
            *(float4*)&cb32[(wr0 + r) * 256 + jb]     = make_float4(o[0], o[1], o[2], o[3]);
            *(float4*)&cb32[(wr0 + r) * 256 + jb + 4] = make_float4(o[4], o[5], o[6], o[7]);
        }
        __syncthreads();
    }

    // ---- per-thread persistent state ----
    const int c2 = (tid & 127) * 2;   // phase-A column pair
    const int rh = tid >> 7;          // 0..3 : rows rh, rh+4, ...
    float2 cb[16];
    {
        const float* cb32 = (const float*)(smc + OFF_X);
        #pragma unroll
        for (int j = 0; j < 16; j++)
            cb[j] = *(const float2*)&cb32[(rh + 4 * j) * 256 + c2];
    }
    __syncthreads();   // X region free for the f16 tile now

    float w1a2[Adim][2], w1t2[2];
    #pragma unroll
    for (int k = 0; k < Adim; k++) {
        w1a2[k][0] = W1[k * Hdim + c2];
        w1a2[k][1] = W1[k * Hdim + c2 + 1];
    }
    w1t2[0] = W1[(Adim + Hdim) * Hdim + c2];
    w1t2[1] = W1[(Adim + Hdim) * Hdim + c2 + 1];
    const float b3_r = b3g[tid & 7];

    // ---- W2^T f16 swizzled [n][k], W3, b2 into smem ----
    for (int idx = tid; idx < Hdim * Hdim; idx += NT) {
        int k = idx >> 8, n = idx & 255;
        uint32_t byte = (uint32_t)((((n >> 3) + ((k >> 6) << 5)) << 10) + ((n & 7) << 7) + ((k & 63) << 1));
        *(__half*)(smc + OFF_W2T + swz(byte)) = __float2half_rn(W2[idx]);
    }
    for (int idx = tid; idx < Hdim * Adim; idx += NT) w3s[idx] = W3g[idx];
    if (tid < Hdim) b2s[tid] = b2g[tid];
    __syncthreads();

    // ---- warp tiling + ldmatrix base offsets ----
    const int m0 = (warp >> 2) * 32;        // X row base (32 rows)
    const int n0 = (warp & 3) * 64;         // output col base (64 cols)
    const int rowA = m0 + ((lane >> 3) & 1) * 8 + (lane & 7);
    const int kA0  = (lane >> 4) * 8;
    uint32_t aoff0 = smb + OFF_X + (((uint32_t)(rowA >> 3)) << 10) + (((uint32_t)(rowA & 7)) << 7)
                   + ((uint32_t)kA0 << 1);
    aoff0 ^= ((uint32_t)(rowA & 7)) << 4;
    const int nB  = n0 + ((lane >> 4) & 1) * 8 + (lane & 7);
    const int kB0 = ((lane >> 3) & 1) * 8;
    uint32_t boff0 = smb + OFF_W2T + (((uint32_t)(nB >> 3)) << 10) + (((uint32_t)(nB & 7)) << 7)
                   + ((uint32_t)kB0 << 1);
    boff0 ^= ((uint32_t)(nB & 7)) << 4;

    const bool zrow = ((lane >> 2) & 1) == 0;          // even X row => h (value) row
    const int  br0  = (m0 >> 1) + ((lane >> 2) >> 1);  // batch row base for epilogue slots
    const float4* pa = (const float4*)a_s;
    const float4* pe = (const float4*)e_s;

    // ================= 50 reverse-Euler steps =================
    for (int step = 0; step < NSTEPS; step++) {
        const float tcur = 1.0f - (float)step * DTC;

        __syncthreads();
        e_s[tid] = eps[(size_t)step * Bsz * Adim + row0 * Adim + tid];
        __syncthreads();

        // ---- phase A: layer-1 value+tangent, silu, write X f16 (rows 2r=h, 2r+1=g) ----
        #pragma unroll
        for (int j = 0; j < 16; j++) {
            const int r = rh + 4 * j;
            float4 a0 = pa[2 * r], a1 = pa[2 * r + 1];
            float4 e0 = pe[2 * r], e1 = pe[2 * r + 1];
            float av[8] = {a0.x, a0.y, a0.z, a0.w, a1.x, a1.y, a1.z, a1.w};
            float ev[8] = {e0.x, e0.y, e0.z, e0.w, e1.x, e1.y, e1.z, e1.w};
            float z0 = cb[j].x + tcur * w1t2[0];
            float z1 = cb[j].y + tcur * w1t2[1];
            float d0 = 0.f, d1 = 0.f;
            #pragma unroll
            for (int k = 0; k < Adim; k++) {
                z0 += av[k] * w1a2[k][0];  z1 += av[k] * w1a2[k][1];
                d0 += ev[k] * w1a2[k][0];  d1 += ev[k] * w1a2[k][1];
            }
            float s0 = 1.0f / (1.0f + __expf(-z0));
            float s1 = 1.0f / (1.0f + __expf(-z1));
            float h0 = z0 * s0, h1v = z1 * s1;
            float g0 = d0 * (s0 * (1.0f + z0 * (1.0f - s0)));
            float g1v = d1 * (s1 * (1.0f + z1 * (1.0f - s1)));
            *(__half2*)(smc + OFF_X + swz(xbyte(2 * r,     c2))) = __floats2half2_rn(h0, h1v);
            *(__half2*)(smc + OFF_X + swz(xbyte(2 * r + 1, c2))) = __floats2half2_rn(g0, g1v);
        }
        __syncthreads();

        // ---- GEMM: D[32x64 per warp] = X @ W2T^T via mma.sync m16n8k16 ----
        float acc[2][8][4];
        #pragma unroll
        for (int mt = 0; mt < 2; mt++)
            #pragma unroll
            for (int nt = 0; nt < 8; nt++)
                #pragma unroll
                for (int i = 0; i < 4; i++) acc[mt][nt][i] = 0.0f;

        #pragma unroll
        for (int kc = 0; kc < 16; kc++) {
            const uint32_t klo = ((uint32_t)(kc & 3)) << 5;
            uint32_t ka = (aoff0 + (((uint32_t)(kc >> 2)) << 14)) ^ klo;
            uint32_t a00, a01, a02, a03, a10, a11, a12, a13;
            ldsm4(a00, a01, a02, a03, ka);
            ldsm4(a10, a11, a12, a13, ka + 2048);   // rows +16
            uint32_t kb = (boff0 + (((uint32_t)(kc >> 2)) << 15)) ^ klo;
            #pragma unroll
            for (int p = 0; p < 4; p++) {
                uint32_t b0, b1, b2r, b3r;
                ldsm4(b0, b1, b2r, b3r, kb + (uint32_t)p * 2048);   // n-tiles 2p, 2p+1
                mma16816(acc[0][2 * p],     a00, a01, a02, a03, b0, b1);
                mma16816(acc[0][2 * p + 1], a00, a01, a02, a03, b2r, b3r);
                mma16816(acc[1][2 * p],     a10, a11, a12, a13, b0, b1);
                mma16816(acc[1][2 * p + 1], a10, a11, a12, a13, b2r, b3r);
            }
        }

        // ---- epilogue (registers): silu'(z2) pairing via shfl, project through W3 ----
        {
            float vj[4][8];
            #pragma unroll
            for (int s = 0; s < 4; s++)
                #pragma unroll
                for (int i = 0; i < 8; i++) vj[s][i] = 0.0f;

            #pragma unroll
            for (int nt = 0; nt < 8; nt++) {
                const int colb = n0 + nt * 8 + (lane & 3) * 2;
                const float b2a = b2s[colb], b2b = b2s[colb + 1];
                float ct[4][2];
                #pragma unroll
                for (int mt = 0; mt < 2; mt++) {
                    float v0 = acc[mt][nt][0], v1 = acc[mt][nt][1];
                    float v2 = acc[mt][nt][2], v3 = acc[mt][nt][3];
                    float z0 = v0 + b2a, z1 = v1 + b2b, z2 = v2 + b2a, z3 = v3 + b2b;
                    float s0 = 1.0f / (1.0f + __expf(-z0));
                    float s1 = 1.0f / (1.0f + __expf(-z1));
                    float s2 = 1.0f / (1.0f + __expf(-z2));
                    float s3 = 1.0f / (1.0f + __expf(-z3));
                    float dc0 = s0 * (1.0f + z0 * (1.0f - s0));
                    float dc1 = s1 * (1.0f + z1 * (1.0f - s1));
                    float dc2 = s2 * (1.0f + z2 * (1.0f - s2));
                    float dc3 = s3 * (1.0f + z3 * (1.0f - s3));
                    float r0 = __shfl_up_sync(0xffffffffu, dc0, 4);
                    float r1 = __shfl_up_sync(0xffffffffu, dc1, 4);
                    float r2 = __shfl_up_sync(0xffffffffu, dc2, 4);
                    float r3 = __shfl_up_sync(0xffffffffu, dc3, 4);
                    ct[mt * 2 + 0][0] = zrow ? z0 * s0 : v0 * r0;
                    ct[mt * 2 + 0][1] = zrow ? z1 * s1 : v1 * r1;
                    ct[mt * 2 + 1][0] = zrow ? z2 * s2 : v2 * r2;
                    ct[mt * 2 + 1][1] = zrow ? z3 * s3 : v3 * r3;
                }
                float4 wa0 = *(const float4*)&w3s[colb * 8];
                float4 wa1 = *(const float4*)&w3s[colb * 8 + 4];
                float4 wb0 = *(const float4*)&w3s[(colb + 1) * 8];
                float4 wb1 = *(const float4*)&w3s[(colb + 1) * 8 + 4];
                #pragma unroll
                for (int s = 0; s < 4; s++) {
                    vj[s][0] += ct[s][0] * wa0.x + ct[s][1] * wb0.x;
                    vj[s][1] += ct[s][0] * wa0.y + ct[s][1] * wb0.y;
                    vj[s][2] += ct[s][0] * wa0.z + ct[s][1] * wb0.z;
                    vj[s][3] += ct[s][0] * wa0.w + ct[s][1] * wb0.w;
                    vj[s][4] += ct[s][0] * wa1.x + ct[s][1] * wb1.x;
                    vj[s][5] += ct[s][0] * wa1.y + ct[s][1] * wb1.y;
                    vj[s][6] += ct[s][0] * wa1.z + ct[s][1] * wb1.z;
                    vj[s][7] += ct[s][0] * wa1.w + ct[s][1] * wb1.w;
                }
            }
            // reduce over the 4 lanes of each quad (same row, different col pairs)
            #pragma unroll
            for (int s = 0; s < 4; s++)
                #pragma unroll
                for (int i = 0; i < 8; i++) {
                    vj[s][i] += __shfl_xor_sync(0xffffffffu, vj[s][i], 1);
                    vj[s][i] += __shfl_xor_sync(0xffffffffu, vj[s][i], 2);
                }
            if ((lane & 3) == 0) {
                float* dst = (zrow ? vp_s : jp_s) + (warp & 3) * 512;
                #pragma unroll
                for (int s = 0; s < 4; s++) {
                    const int row = br0 + (s & 1) * 4 + (s >> 1) * 8;
                    *(float4*)&dst[row * 8]     = make_float4(vj[s][0], vj[s][1], vj[s][2], vj[s][3]);
                    *(float4*)&dst[row * 8 + 4] = make_float4(vj[s][4], vj[s][5], vj[s][6], vj[s][7]);
                }
            }
        }
        __syncthreads();

        // ---- update: reduce 4 n-groups, Euler step, divergence integral ----
        {
            const int ur = tid >> 3, ui = tid & 7;
            float v = b3_r, jv = 0.0f;
            #pragma unroll
            for (int g = 0; g < 4; g++) {
                v  += vp_s[g * 512 + ur * 8 + ui];
                jv += jp_s[g * 512 + ur * 8 + ui];
            }
            float dp = jv * e_s[ur * 8 + ui];
            dp += __shfl_xor_sync(0xffffffffu, dp, 1);
            dp += __shfl_xor_sync(0xffffffffu, dp, 2);
            dp += __shfl_xor_sync(0xffffffffu, dp, 4);
            a_s[ur * 8 + ui] -= v * DTC;
            if (ui == 0) di_s[ur] += dp * DTC;
        }
    }

    // ================= output =================
    __syncthreads();
    if (tid < TB) {
        float s2 = 0.0f;
        #pragma unroll
        for (int i = 0; i < Adim; i++) {
            float av = a_s[tid * Adim + i];
            s2 += av * av;
        }
        out[row0 + tid] = -0.5f * (s2 + (float)Adim * 1.8378770664093453f) - di_s[tid];
    }
}

extern "C" void kernel_launch(void* const* d_in, const int* in_sizes, int n_in,
                              void* d_out, int out_size) {
    (void)in_sizes; (void)n_in; (void)out_size;
    cudaFuncSetAttribute(fm_logp_kernel,
                         cudaFuncAttributeMaxDynamicSharedMemorySize, SMEM_BYTES);
    fm_logp_kernel<<<Bsz / TB, NT, SMEM_BYTES>>>(
        (const float*)d_in[0], (const float*)d_in[1], (const float*)d_in[2],
        (const float*)d_in[3], (const float*)d_in[4], (const float*)d_in[5],
        (const float*)d_in[6], (const float*)d_in[7], (const float*)d_in[8],
        (float*)d_out);
}